// round 3
// baseline (speedup 1.0000x reference)
#include <cuda_runtime.h>
#include <cuda_bf16.h>
#include <cstdint>
#include <math.h>

// ---------- problem constants ----------
#define BB    8
#define CC    192
#define HH    128
#define WWI   128
#define NTOK  (BB*HH*WWI)      // 131072
#define NHEAD 8
#define HD    24
#define WS    8
#define LW    (WS*WS)
#define NWIN  (BB*(HH/WS)*(WWI/WS))
#define FFND  768
#define C3    (3*CC)
#define SCALE_ATT 0.20412414523193150818f

// GEMM tiling
#define TM 128
#define TN 64

// weight offsets in packed hi/lo weight buffers
#define W_SAQKV 0
#define W_SAPRJ 110592
#define W_CAQKV 147456
#define W_CAPRJ 258048
#define W_FFN1  294912
#define W_FFN2  442368
#define W_TOT   589824

// ---------- scratch ----------
__device__ __align__(256) float g_xt [NTOK*CC];
__device__ __align__(256) float g_qkv[(size_t)NTOK*C3];
__device__ __align__(256) __nv_bfloat16 g_ah[(size_t)NTOK*CC];
__device__ __align__(256) __nv_bfloat16 g_al[(size_t)NTOK*CC];
__device__ __align__(256) __nv_bfloat16 g_hh[(size_t)NTOK*FFND];
__device__ __align__(256) __nv_bfloat16 g_hl[(size_t)NTOK*FFND];
__device__ __align__(256) __nv_bfloat16 g_wh[W_TOT];
__device__ __align__(256) __nv_bfloat16 g_wl[W_TOT];
__device__ __align__(256) float g_gram[BB*NHEAD*HD*HD];
__device__ __align__(256) float g_attn[BB*NHEAD*HD*HD];

// ---------- helpers ----------
__device__ __forceinline__ float gelu_f(float x){
    return 0.5f * x * (1.f + erff(x * 0.70710678118654752440f));
}
__device__ __forceinline__ void split_store(float v, __nv_bfloat16* hi, __nv_bfloat16* lo, size_t idx){
    __nv_bfloat16 h = __float2bfloat16(v);
    hi[idx] = h;
    lo[idx] = __float2bfloat16(v - __bfloat162float(h));
}
__device__ __forceinline__ void mma16816(float* c, const uint32_t* a, const uint32_t* b){
    asm volatile(
        "mma.sync.aligned.m16n8k16.row.col.f32.bf16.bf16.f32 "
        "{%0,%1,%2,%3}, {%4,%5,%6,%7}, {%8,%9}, {%0,%1,%2,%3};"
        : "+f"(c[0]), "+f"(c[1]), "+f"(c[2]), "+f"(c[3])
        : "r"(a[0]), "r"(a[1]), "r"(a[2]), "r"(a[3]), "r"(b[0]), "r"(b[1]));
}

// ---------- weight split ----------
__global__ void wconv_kernel(const float* __restrict__ w, __nv_bfloat16* hi, __nv_bfloat16* lo, int n){
    int i = blockIdx.x*256 + threadIdx.x;
    if (i < n){
        float x = w[i];
        __nv_bfloat16 h = __float2bfloat16(x);
        hi[i] = h;
        lo[i] = __float2bfloat16(x - __bfloat162float(h));
    }
}

// ---------- NCHW <-> NHWC ----------
__global__ void nchw_to_nhwc(const float* __restrict__ x, float* __restrict__ xt){
    __shared__ float tile[32][33];
    int bh = blockIdx.z; int b = bh / HH; int h = bh % HH;
    int w0 = blockIdx.x*32, c0 = blockIdx.y*32;
    const float* xb = x + (size_t)b*CC*HH*WWI + (size_t)h*WWI;
    #pragma unroll
    for (int k=0;k<4;k++){
        int c = c0 + threadIdx.y + k*8;
        tile[threadIdx.y + k*8][threadIdx.x] = xb[(size_t)c*HH*WWI + w0 + threadIdx.x];
    }
    __syncthreads();
    size_t nbase = ((size_t)b*HH + h)*WWI;
    #pragma unroll
    for (int k=0;k<4;k++){
        int w = w0 + threadIdx.y + k*8;
        xt[(nbase + w)*CC + c0 + threadIdx.x] = tile[threadIdx.x][threadIdx.y + k*8];
    }
}
__global__ void nhwc_to_nchw(const float* __restrict__ xt, float* __restrict__ y){
    __shared__ float tile[32][33];
    int bh = blockIdx.z; int b = bh / HH; int h = bh % HH;
    int w0 = blockIdx.x*32, c0 = blockIdx.y*32;
    size_t nbase = ((size_t)b*HH + h)*WWI;
    #pragma unroll
    for (int k=0;k<4;k++){
        int w = w0 + threadIdx.y + k*8;
        tile[threadIdx.y + k*8][threadIdx.x] = xt[(nbase + w)*CC + c0 + threadIdx.x];
    }
    __syncthreads();
    #pragma unroll
    for (int k=0;k<4;k++){
        int c = c0 + threadIdx.y + k*8;
        y[((size_t)(b*CC + c)*HH + h)*WWI + w0 + threadIdx.x] = tile[threadIdx.x][threadIdx.y + k*8];
    }
}

// ---------- LayerNorm -> split bf16 ----------
__global__ void ln_kernel(const float* __restrict__ xin, const float* __restrict__ w,
                          const float* __restrict__ b,
                          __nv_bfloat16* __restrict__ ohi, __nv_bfloat16* __restrict__ olo){
    int warp = threadIdx.x >> 5, lane = threadIdx.x & 31;
    size_t row = (size_t)blockIdx.x*4 + warp;
    const float* xr = xin + row*CC;
    float v[6]; float s = 0.f, s2 = 0.f;
    #pragma unroll
    for (int i=0;i<6;i++){ v[i] = xr[lane + i*32]; s += v[i]; s2 += v[i]*v[i]; }
    #pragma unroll
    for (int o=16;o;o>>=1){ s += __shfl_xor_sync(~0u, s, o); s2 += __shfl_xor_sync(~0u, s2, o); }
    float m  = s * (1.f/CC);
    float var = s2*(1.f/CC) - m*m;
    float rs = rsqrtf(var + 1e-5f);
    #pragma unroll
    for (int i=0;i<6;i++){
        int c = lane + i*32;
        float yv = (v[i]-m)*rs*w[c] + b[c];
        split_store(yv, ohi, olo, row*CC + c);
    }
}

// ---------- mma.sync split-bf16 GEMM ----------
// D[TM, TN] = A[N,K] @ W[Of,K]^T, 3-term split: AhWh + AlWh + AhWl
// EPI 0: fp32 out  EPI 1: gelu -> hi/lo bf16  EPI 2: resid += gamma*(acc+bias)
template<int EPI>
__global__ __launch_bounds__(128) void gemm_mma(
    const __nv_bfloat16* __restrict__ a_hi, const __nv_bfloat16* __restrict__ a_lo,
    const __nv_bfloat16* __restrict__ w_hi, const __nv_bfloat16* __restrict__ w_lo,
    const float* __restrict__ bias, float* __restrict__ outf,
    __nv_bfloat16* __restrict__ oh, __nv_bfloat16* __restrict__ ol,
    const float* __restrict__ gamma, float* __restrict__ resid,
    int K, int ldo)
{
    // fragment-layout smem: A[buf][term][8 mblk][32 lane][4 regs], B[buf][term][8 nblk][32 lane][2 regs]
    __shared__ uint32_t sA[2][2][1024];
    __shared__ uint32_t sB[2][2][512];

    const int t = threadIdx.x;
    const int warp = t >> 5, lane = t & 31;
    const int wm = (warp >> 1) * 64;     // warp row offset in tile
    const int wn = (warp & 1) * 32;      // warp col offset
    const size_t m0 = (size_t)blockIdx.y * TM;
    const int n0 = blockIdx.x * TN;
    const int Kw = K >> 1;               // words per row

    const uint32_t* gAh = (const uint32_t*)a_hi;
    const uint32_t* gAl = (const uint32_t*)a_lo;
    const uint32_t* gBh = (const uint32_t*)w_hi;
    const uint32_t* gBl = (const uint32_t*)w_lo;

    float acc[4][4][4];
    #pragma unroll
    for (int i=0;i<4;i++)
        #pragma unroll
        for (int j=0;j<4;j++)
            #pragma unroll
            for (int c=0;c<4;c++) acc[i][j][c] = 0.f;

    uint32_t ra_h[8], ra_l[8], rb_h[4], rb_l[4];

    // precompute scatter offsets
    int aoff[8], boff[4];
    size_t agidx[8]; size_t bgidx[4];
    #pragma unroll
    for (int i=0;i<8;i++){
        int w = t + i*128, m = w>>3, kp = w&7;
        aoff[i] = (m>>4)*128 + ((m&7)*4 + (kp&3))*4 + ((m>>3)&1) + 2*(kp>>2);
        agidx[i] = (m0 + m)*(size_t)Kw + kp;
    }
    #pragma unroll
    for (int i=0;i<4;i++){
        int w = t + i*128, n = w>>3, kp = w&7;
        boff[i] = (n>>3)*64 + ((n&7)*4 + (kp&3))*2 + (kp>>2);
        bgidx[i] = (size_t)(n0 + n)*Kw + kp;
    }

    const int nk = K >> 4;

    // prologue load k-step 0
    #pragma unroll
    for (int i=0;i<8;i++){ ra_h[i] = gAh[agidx[i]]; ra_l[i] = gAl[agidx[i]]; }
    #pragma unroll
    for (int i=0;i<4;i++){ rb_h[i] = gBh[bgidx[i]]; rb_l[i] = gBl[bgidx[i]]; }
    #pragma unroll
    for (int i=0;i<8;i++){ sA[0][0][aoff[i]] = ra_h[i]; sA[0][1][aoff[i]] = ra_l[i]; }
    #pragma unroll
    for (int i=0;i<4;i++){ sB[0][0][boff[i]] = rb_h[i]; sB[0][1][boff[i]] = rb_l[i]; }
    __syncthreads();

    for (int k = 0; k < nk; k++){
        int cur = k & 1, nxt = cur ^ 1;
        if (k+1 < nk){
            size_t ko = (size_t)(k+1)*8;
            #pragma unroll
            for (int i=0;i<8;i++){ ra_h[i] = gAh[agidx[i]+ko]; ra_l[i] = gAl[agidx[i]+ko]; }
            #pragma unroll
            for (int i=0;i<4;i++){ rb_h[i] = gBh[bgidx[i]+ko]; rb_l[i] = gBl[bgidx[i]+ko]; }
        }
        // 3 terms: (Ah,Bh), (Al,Bh), (Ah,Bl)
        #pragma unroll
        for (int term=0; term<3; term++){
            const uint32_t* As = sA[cur][term==1 ? 1 : 0];
            const uint32_t* Bs = sB[cur][term==2 ? 1 : 0];
            uint32_t bf[4][2];
            #pragma unroll
            for (int bn=0;bn<4;bn++){
                int nb = (wn>>3) + bn;
                uint2 v = *(const uint2*)&Bs[nb*64 + lane*2];
                bf[bn][0] = v.x; bf[bn][1] = v.y;
            }
            #pragma unroll
            for (int bm=0;bm<4;bm++){
                int mb = (wm>>4) + bm;
                uint4 av = *(const uint4*)&As[mb*128 + lane*4];
                uint32_t af[4] = {av.x, av.y, av.z, av.w};
                #pragma unroll
                for (int bn=0;bn<4;bn++)
                    mma16816(acc[bm][bn], af, bf[bn]);
            }
        }
        if (k+1 < nk){
            #pragma unroll
            for (int i=0;i<8;i++){ sA[nxt][0][aoff[i]] = ra_h[i]; sA[nxt][1][aoff[i]] = ra_l[i]; }
            #pragma unroll
            for (int i=0;i<4;i++){ sB[nxt][0][boff[i]] = rb_h[i]; sB[nxt][1][boff[i]] = rb_l[i]; }
        }
        __syncthreads();
    }

    // ---------- epilogue ----------
    const int r0 = lane >> 2;
    const int cp = (lane & 3) * 2;
    #pragma unroll
    for (int bm=0;bm<4;bm++){
        #pragma unroll
        for (int bn=0;bn<4;bn++){
            int n = n0 + wn + bn*8 + cp;
            size_t mA = m0 + wm + bm*16 + r0;
            size_t mB = mA + 8;
            float c0 = acc[bm][bn][0], c1 = acc[bm][bn][1];
            float c2 = acc[bm][bn][2], c3 = acc[bm][bn][3];
            if (EPI == 0){
                *(float2*)(outf + mA*(size_t)ldo + n) = make_float2(c0, c1);
                *(float2*)(outf + mB*(size_t)ldo + n) = make_float2(c2, c3);
            } else if (EPI == 1){
                float b0 = bias[n], b1 = bias[n+1];
                split_store(gelu_f(c0 + b0), oh, ol, mA*(size_t)ldo + n);
                split_store(gelu_f(c1 + b1), oh, ol, mA*(size_t)ldo + n + 1);
                split_store(gelu_f(c2 + b0), oh, ol, mB*(size_t)ldo + n);
                split_store(gelu_f(c3 + b1), oh, ol, mB*(size_t)ldo + n + 1);
            } else {
                float b0 = bias[n], b1 = bias[n+1];
                float g0 = gamma[n], g1 = gamma[n+1];
                float2* pA = (float2*)(resid + mA*(size_t)CC + n);
                float2* pB = (float2*)(resid + mB*(size_t)CC + n);
                float2 vA = *pA, vB = *pB;
                vA.x += g0*(c0 + b0); vA.y += g1*(c1 + b1);
                vB.x += g0*(c2 + b0); vB.y += g1*(c3 + b1);
                *pA = vA; *pB = vB;
            }
        }
    }
}

// ---------- spatial window attention (fp32 in, split bf16 out) ----------
__global__ __launch_bounds__(64) void sa_attn_kernel(const float* __restrict__ qkv,
                                                     const float* __restrict__ btab,
                                                     __nv_bfloat16* __restrict__ ohi,
                                                     __nv_bfloat16* __restrict__ olo){
    __shared__ __align__(16) float qs[LW*HD];
    __shared__ __align__(16) float ks[LW*HD];
    __shared__ __align__(16) float vs[LW*HD];
    __shared__ float bt[225];
    int win = blockIdx.x, hh = blockIdx.y;
    int l = threadIdx.x;
    int b = win >> 8;
    int wrem = win & 255;
    int wh = wrem >> 4, ww = wrem & 15;
    int i = l >> 3, j = l & 7;
    size_t n = ((size_t)(b*HH) + wh*WS + i)*WWI + ww*WS + j;

    const float4* qp = (const float4*)(qkv + n*C3 +        hh*HD);
    const float4* kp = (const float4*)(qkv + n*C3 + CC   + hh*HD);
    const float4* vp = (const float4*)(qkv + n*C3 + 2*CC + hh*HD);
    float4* qd = (float4*)&qs[l*HD];
    float4* kd = (float4*)&ks[l*HD];
    float4* vd = (float4*)&vs[l*HD];
    #pragma unroll
    for (int u=0;u<6;u++){ qd[u]=qp[u]; kd[u]=kp[u]; vd[u]=vp[u]; }
    for (int tt=l; tt<225; tt+=64) bt[tt] = btab[tt*NHEAD + hh];
    __syncthreads();

    float4 qf[6];
    #pragma unroll
    for (int u=0;u<6;u++) qf[u] = ((const float4*)&qs[l*HD])[u];

    float s[LW];
    #pragma unroll
    for (int m=0;m<LW;m++){
        const float4* kr = (const float4*)&ks[m*HD];
        float a = 0.f;
        #pragma unroll
        for (int u=0;u<6;u++){
            float4 kv = kr[u];
            a = fmaf(qf[u].x,kv.x, fmaf(qf[u].y,kv.y, fmaf(qf[u].z,kv.z, fmaf(qf[u].w,kv.w, a))));
        }
        int mi = m>>3, mj = m&7;
        s[m] = a*SCALE_ATT + bt[(i-mi+7)*15 + (j-mj+7)];
    }
    float mx = s[0];
    #pragma unroll
    for (int m=1;m<LW;m++) mx = fmaxf(mx, s[m]);
    float sum = 0.f;
    #pragma unroll
    for (int m=0;m<LW;m++){ s[m] = __expf(s[m]-mx); sum += s[m]; }
    float inv = 1.f/sum;

    float o[HD];
    #pragma unroll
    for (int u=0;u<HD;u++) o[u] = 0.f;
    #pragma unroll
    for (int m=0;m<LW;m++){
        float p = s[m];
        const float* vr = &vs[m*HD];
        #pragma unroll
        for (int u=0;u<HD;u++) o[u] = fmaf(p, vr[u], o[u]);
    }
    size_t ob = n*CC + hh*HD;
    #pragma unroll
    for (int u=0;u<HD;u++) split_store(o[u]*inv, ohi, olo, ob + u);
}

// ---------- channel attention ----------
__global__ void zero_kernel(float* p, int n){
    int idx = blockIdx.x*blockDim.x + threadIdx.x;
    if (idx < n) p[idx] = 0.f;
}
__global__ __launch_bounds__(256) void ca_gram_kernel(const float* __restrict__ qkv,
                                                      float* __restrict__ gram){
    __shared__ __align__(16) float qs[256*HD];
    __shared__ __align__(16) float ks[256*HD];
    int bh = blockIdx.y; int b = bh >> 3; int hh = bh & 7;
    int chunk = blockIdx.x;
    int t = threadIdx.x;
    size_t n = (size_t)b*(HH*WWI) + (size_t)chunk*256 + t;
    const float4* qp = (const float4*)(qkv + n*C3 +      hh*HD);
    const float4* kp = (const float4*)(qkv + n*C3 + CC + hh*HD);
    float4* qd = (float4*)&qs[t*HD];
    float4* kd = (float4*)&ks[t*HD];
    #pragma unroll
    for (int u=0;u<6;u++){ qd[u]=qp[u]; kd[u]=kp[u]; }
    __syncthreads();

    int p0 = t, p1 = t + 256, p2 = t + 512;
    int d0 = p0/HD, e0 = p0 - d0*HD;
    int d1 = p1/HD, e1 = p1 - d1*HD;
    int d2 = p2/HD, e2 = p2 - d2*HD;
    bool has2 = (p2 < 576);
    float a0=0.f, a1=0.f, a2=0.f;
    for (int l=0;l<256;l++){
        const float* qrow = &qs[l*HD];
        const float* krow = &ks[l*HD];
        a0 = fmaf(qrow[d0], krow[e0], a0);
        a1 = fmaf(qrow[d1], krow[e1], a1);
        if (has2) a2 = fmaf(qrow[d2], krow[e2], a2);
    }
    atomicAdd(&gram[bh*576 + p0], a0);
    atomicAdd(&gram[bh*576 + p1], a1);
    if (has2) atomicAdd(&gram[bh*576 + p2], a2);
}
__global__ void ca_softmax_kernel(const float* __restrict__ gram, float* __restrict__ attn){
    int bh = blockIdx.x; int d = threadIdx.x;
    if (d >= HD) return;
    const float* r = gram + bh*576 + d*HD;
    float v[HD];
    float mx = -1e30f;
    #pragma unroll
    for (int e=0;e<HD;e++){ v[e] = r[e]*SCALE_ATT; mx = fmaxf(mx, v[e]); }
    float sum = 0.f;
    #pragma unroll
    for (int e=0;e<HD;e++){ v[e] = __expf(v[e]-mx); sum += v[e]; }
    float inv = 1.f/sum;
    #pragma unroll
    for (int e=0;e<HD;e++) attn[bh*576 + d*HD + e] = v[e]*inv;
}
__global__ __launch_bounds__(192) void ca_apply_kernel(const float* __restrict__ qkv,
                                                       const float* __restrict__ attn,
                                                       __nv_bfloat16* __restrict__ ohi,
                                                       __nv_bfloat16* __restrict__ olo){
    __shared__ float at[NHEAD*HD*HD];
    __shared__ float vsm[CC];
    int t = threadIdx.x;
    size_t n0 = (size_t)blockIdx.x * 32;
    int b = (int)(n0 >> 14);
    for (int idx=t; idx<NHEAD*HD*HD; idx+=192) at[idx] = attn[(size_t)b*NHEAD*HD*HD + idx];
    __syncthreads();
    int hh = t / HD, d = t - hh*HD;
    float ar[HD];
    #pragma unroll
    for (int e=0;e<HD;e++) ar[e] = at[hh*576 + d*HD + e];
    for (int tok=0; tok<32; tok++){
        size_t n = n0 + tok;
        __syncthreads();
        vsm[t] = qkv[n*C3 + 2*CC + t];
        __syncthreads();
        float o = 0.f;
        #pragma unroll
        for (int e=0;e<HD;e++) o = fmaf(ar[e], vsm[hh*HD + e], o);
        split_store(o, ohi, olo, n*CC + t);
    }
}

// ---------- launch ----------
extern "C" void kernel_launch(void* const* d_in, const int* in_sizes, int n_in,
                              void* d_out, int out_size)
{
    const float* x           = (const float*)d_in[0];
    const float* sa_norm_w   = (const float*)d_in[1];
    const float* sa_norm_b   = (const float*)d_in[2];
    const float* sa_qkv_w    = (const float*)d_in[3];
    const float* sa_proj_w   = (const float*)d_in[4];
    const float* sa_proj_b   = (const float*)d_in[5];
    const float* sa_bias_tab = (const float*)d_in[6];
    const float* ca_norm_w   = (const float*)d_in[7];
    const float* ca_norm_b   = (const float*)d_in[8];
    const float* ca_qkv_w    = (const float*)d_in[9];
    const float* ca_proj_w   = (const float*)d_in[10];
    const float* ca_proj_b   = (const float*)d_in[11];
    const float* ffn_norm_w  = (const float*)d_in[12];
    const float* ffn_norm_b  = (const float*)d_in[13];
    const float* ffn_w1      = (const float*)d_in[14];
    const float* ffn_b1      = (const float*)d_in[15];
    const float* ffn_w2      = (const float*)d_in[16];
    const float* ffn_b2      = (const float*)d_in[17];
    const float* gamma1      = (const float*)d_in[18];
    const float* gamma2      = (const float*)d_in[19];
    const float* gamma3      = (const float*)d_in[20];
    float* y = (float*)d_out;

    float *xt, *qkv, *gram, *attn;
    __nv_bfloat16 *ah, *al, *fh, *fl, *wh, *wl;
    cudaGetSymbolAddress((void**)&xt,   g_xt);
    cudaGetSymbolAddress((void**)&qkv,  g_qkv);
    cudaGetSymbolAddress((void**)&gram, g_gram);
    cudaGetSymbolAddress((void**)&attn, g_attn);
    cudaGetSymbolAddress((void**)&ah,   g_ah);
    cudaGetSymbolAddress((void**)&al,   g_al);
    cudaGetSymbolAddress((void**)&fh,   g_hh);
    cudaGetSymbolAddress((void**)&fl,   g_hl);
    cudaGetSymbolAddress((void**)&wh,   g_wh);
    cudaGetSymbolAddress((void**)&wl,   g_wl);

    // split weights to bf16 hi/lo
    wconv_kernel<<<(110592+255)/256,256>>>(sa_qkv_w,  wh+W_SAQKV, wl+W_SAQKV, 110592);
    wconv_kernel<<<(36864 +255)/256,256>>>(sa_proj_w, wh+W_SAPRJ, wl+W_SAPRJ, 36864);
    wconv_kernel<<<(110592+255)/256,256>>>(ca_qkv_w,  wh+W_CAQKV, wl+W_CAQKV, 110592);
    wconv_kernel<<<(36864 +255)/256,256>>>(ca_proj_w, wh+W_CAPRJ, wl+W_CAPRJ, 36864);
    wconv_kernel<<<(147456+255)/256,256>>>(ffn_w1,    wh+W_FFN1,  wl+W_FFN1,  147456);
    wconv_kernel<<<(147456+255)/256,256>>>(ffn_w2,    wh+W_FFN2,  wl+W_FFN2,  147456);

    dim3 tb(32,8);
    dim3 tg(WWI/32, CC/32, BB*HH);
    nchw_to_nhwc<<<tg, tb>>>(x, xt);

    const int MT = NTOK/TM;   // 1024

    // ---- spatial window attention ----
    ln_kernel<<<NTOK/4, 128>>>(xt, sa_norm_w, sa_norm_b, ah, al);
    gemm_mma<0><<<dim3(C3/TN, MT), 128>>>(ah, al, wh+W_SAQKV, wl+W_SAQKV,
        nullptr, qkv, nullptr, nullptr, nullptr, nullptr, CC, C3);
    sa_attn_kernel<<<dim3(NWIN, NHEAD), 64>>>(qkv, sa_bias_tab, ah, al);
    gemm_mma<2><<<dim3(CC/TN, MT), 128>>>(ah, al, wh+W_SAPRJ, wl+W_SAPRJ,
        sa_proj_b, nullptr, nullptr, nullptr, gamma1, xt, CC, CC);

    // ---- channel attention ----
    ln_kernel<<<NTOK/4, 128>>>(xt, ca_norm_w, ca_norm_b, ah, al);
    gemm_mma<0><<<dim3(C3/TN, MT), 128>>>(ah, al, wh+W_CAQKV, wl+W_CAQKV,
        nullptr, qkv, nullptr, nullptr, nullptr, nullptr, CC, C3);
    zero_kernel<<<(BB*NHEAD*HD*HD + 255)/256, 256>>>(gram, BB*NHEAD*HD*HD);
    ca_gram_kernel<<<dim3(64, BB*NHEAD), 256>>>(qkv, gram);
    ca_softmax_kernel<<<BB*NHEAD, 32>>>(gram, attn);
    ca_apply_kernel<<<NTOK/32, 192>>>(qkv, attn, ah, al);
    gemm_mma<2><<<dim3(CC/TN, MT), 128>>>(ah, al, wh+W_CAPRJ, wl+W_CAPRJ,
        ca_proj_b, nullptr, nullptr, nullptr, gamma2, xt, CC, CC);

    // ---- gated FFN ----
    ln_kernel<<<NTOK/4, 128>>>(xt, ffn_norm_w, ffn_norm_b, ah, al);
    gemm_mma<1><<<dim3(FFND/TN, MT), 128>>>(ah, al, wh+W_FFN1, wl+W_FFN1,
        ffn_b1, nullptr, fh, fl, nullptr, nullptr, CC, FFND);
    gemm_mma<2><<<dim3(CC/TN, MT), 128>>>(fh, fl, wh+W_FFN2, wl+W_FFN2,
        ffn_b2, nullptr, nullptr, nullptr, gamma3, xt, FFND, CC);

    nhwc_to_nchw<<<tg, tb>>>(xt, y);
}

// round 4
// speedup vs baseline: 1.5059x; 1.5059x over previous
#include <cuda_runtime.h>
#include <cuda_bf16.h>
#include <cstdint>
#include <math.h>

// ---------- problem constants ----------
#define BB    8
#define CC    192
#define HH    128
#define WWI   128
#define NTOK  (BB*HH*WWI)      // 131072
#define NHEAD 8
#define HD    24
#define WS    8
#define LW    (WS*WS)
#define NWIN  (BB*(HH/WS)*(WWI/WS))
#define FFND  768
#define C3    (3*CC)
#define SCALE_ATT 0.20412414523193150818f

// GEMM tiling
#define TM 128
#define TN 64
#define NSTAGE 3
#define STAGE_BYTES 12288      // Ah 4K + Al 4K + Bh 2K + Bl 2K

// weight offsets in packed hi/lo weight buffers
#define W_SAQKV 0
#define W_SAPRJ 110592
#define W_CAQKV 147456
#define W_CAPRJ 258048
#define W_FFN1  294912
#define W_FFN2  442368
#define W_TOT   589824

// ---------- scratch ----------
__device__ __align__(256) float g_xt [NTOK*CC];
__device__ __align__(256) float g_qkv[(size_t)NTOK*C3];
__device__ __align__(256) __nv_bfloat16 g_ah[(size_t)NTOK*CC];
__device__ __align__(256) __nv_bfloat16 g_al[(size_t)NTOK*CC];
__device__ __align__(256) __nv_bfloat16 g_hh[(size_t)NTOK*FFND];
__device__ __align__(256) __nv_bfloat16 g_hl[(size_t)NTOK*FFND];
__device__ __align__(256) __nv_bfloat16 g_wh[W_TOT];
__device__ __align__(256) __nv_bfloat16 g_wl[W_TOT];
__device__ __align__(256) float g_gram[BB*NHEAD*HD*HD];
__device__ __align__(256) float g_attn[BB*NHEAD*HD*HD];

// ---------- helpers ----------
__device__ __forceinline__ float gelu_f(float x){
    return 0.5f * x * (1.f + erff(x * 0.70710678118654752440f));
}
__device__ __forceinline__ void split_store(float v, __nv_bfloat16* hi, __nv_bfloat16* lo, size_t idx){
    __nv_bfloat16 h = __float2bfloat16(v);
    hi[idx] = h;
    lo[idx] = __float2bfloat16(v - __bfloat162float(h));
}
__device__ __forceinline__ uint32_t smem_u32(const void* p){
    uint32_t a;
    asm("{ .reg .u64 t; cvta.to.shared.u64 t, %1; cvt.u32.u64 %0, t; }" : "=r"(a) : "l"(p));
    return a;
}
__device__ __forceinline__ void mma16816(float* c, const uint32_t* a, const uint32_t* b){
    asm volatile(
        "mma.sync.aligned.m16n8k16.row.col.f32.bf16.bf16.f32 "
        "{%0,%1,%2,%3}, {%4,%5,%6,%7}, {%8,%9}, {%0,%1,%2,%3};"
        : "+f"(c[0]), "+f"(c[1]), "+f"(c[2]), "+f"(c[3])
        : "r"(a[0]), "r"(a[1]), "r"(a[2]), "r"(a[3]), "r"(b[0]), "r"(b[1]));
}
__device__ __forceinline__ void cp_async16(uint32_t dst, const void* src){
    asm volatile("cp.async.cg.shared.global [%0], [%1], 16;" :: "r"(dst), "l"(src));
}
#define CP_COMMIT() asm volatile("cp.async.commit_group;" ::: "memory")
#define CP_WAIT1()  asm volatile("cp.async.wait_group 1;" ::: "memory")
#define LDM4(r, addr) \
    asm volatile("ldmatrix.sync.aligned.m8n8.x4.shared.b16 {%0,%1,%2,%3}, [%4];" \
        : "=r"((r)[0]), "=r"((r)[1]), "=r"((r)[2]), "=r"((r)[3]) : "r"(addr))

// ---------- weight split (single launch) ----------
struct WSrc { const float* p[6]; };
__global__ void wconv_all(WSrc s, __nv_bfloat16* hi, __nv_bfloat16* lo){
    int i = blockIdx.x*256 + threadIdx.x;
    if (i >= W_TOT) return;
    const int off1 = W_SAPRJ, off2 = W_CAQKV, off3 = W_CAPRJ, off4 = W_FFN1, off5 = W_FFN2;
    int r = 0, base = 0;
    if (i >= off5){ r = 5; base = off5; }
    else if (i >= off4){ r = 4; base = off4; }
    else if (i >= off3){ r = 3; base = off3; }
    else if (i >= off2){ r = 2; base = off2; }
    else if (i >= off1){ r = 1; base = off1; }
    float x = s.p[r][i - base];
    __nv_bfloat16 h = __float2bfloat16(x);
    hi[i] = h;
    lo[i] = __float2bfloat16(x - __bfloat162float(h));
}

// ---------- NCHW <-> NHWC ----------
__global__ void nchw_to_nhwc(const float* __restrict__ x, float* __restrict__ xt){
    __shared__ float tile[32][33];
    int bh = blockIdx.z; int b = bh / HH; int h = bh % HH;
    int w0 = blockIdx.x*32, c0 = blockIdx.y*32;
    const float* xb = x + (size_t)b*CC*HH*WWI + (size_t)h*WWI;
    #pragma unroll
    for (int k=0;k<4;k++){
        int c = c0 + threadIdx.y + k*8;
        tile[threadIdx.y + k*8][threadIdx.x] = xb[(size_t)c*HH*WWI + w0 + threadIdx.x];
    }
    __syncthreads();
    size_t nbase = ((size_t)b*HH + h)*WWI;
    #pragma unroll
    for (int k=0;k<4;k++){
        int w = w0 + threadIdx.y + k*8;
        xt[(nbase + w)*CC + c0 + threadIdx.x] = tile[threadIdx.x][threadIdx.y + k*8];
    }
}
__global__ void nhwc_to_nchw(const float* __restrict__ xt, float* __restrict__ y){
    __shared__ float tile[32][33];
    int bh = blockIdx.z; int b = bh / HH; int h = bh % HH;
    int w0 = blockIdx.x*32, c0 = blockIdx.y*32;
    size_t nbase = ((size_t)b*HH + h)*WWI;
    #pragma unroll
    for (int k=0;k<4;k++){
        int w = w0 + threadIdx.y + k*8;
        tile[threadIdx.y + k*8][threadIdx.x] = xt[(nbase + w)*CC + c0 + threadIdx.x];
    }
    __syncthreads();
    #pragma unroll
    for (int k=0;k<4;k++){
        int c = c0 + threadIdx.y + k*8;
        y[((size_t)(b*CC + c)*HH + h)*WWI + w0 + threadIdx.x] = tile[threadIdx.x][threadIdx.y + k*8];
    }
}

// ---------- LayerNorm -> split bf16 ----------
__global__ void ln_kernel(const float* __restrict__ xin, const float* __restrict__ w,
                          const float* __restrict__ b,
                          __nv_bfloat16* __restrict__ ohi, __nv_bfloat16* __restrict__ olo){
    int warp = threadIdx.x >> 5, lane = threadIdx.x & 31;
    size_t row = (size_t)blockIdx.x*4 + warp;
    const float* xr = xin + row*CC;
    float v[6]; float s = 0.f, s2 = 0.f;
    #pragma unroll
    for (int i=0;i<6;i++){ v[i] = xr[lane + i*32]; s += v[i]; s2 += v[i]*v[i]; }
    #pragma unroll
    for (int o=16;o;o>>=1){ s += __shfl_xor_sync(~0u, s, o); s2 += __shfl_xor_sync(~0u, s2, o); }
    float m  = s * (1.f/CC);
    float var = s2*(1.f/CC) - m*m;
    float rs = rsqrtf(var + 1e-5f);
    #pragma unroll
    for (int i=0;i<6;i++){
        int c = lane + i*32;
        float yv = (v[i]-m)*rs*w[c] + b[c];
        split_store(yv, ohi, olo, row*CC + c);
    }
}

// ---------- pipelined mma.sync split-bf16 GEMM ----------
// D = A[N,K] @ W[Of,K]^T, 3 terms: AhWh + AlWh + AhWl
// EPI 0: fp32 out  EPI 1: gelu -> hi/lo bf16  EPI 2: resid += gamma*(acc+bias)
template<int EPI>
__global__ __launch_bounds__(256, 2) void gemm_mma(
    const __nv_bfloat16* __restrict__ a_hi, const __nv_bfloat16* __restrict__ a_lo,
    const __nv_bfloat16* __restrict__ w_hi, const __nv_bfloat16* __restrict__ w_lo,
    const float* __restrict__ bias, float* __restrict__ outf,
    __nv_bfloat16* __restrict__ oh, __nv_bfloat16* __restrict__ ol,
    const float* __restrict__ gamma, float* __restrict__ resid,
    int K, int ldo)
{
    // per stage: [Ah 128x2x16B | Al | Bh 64x2x16B | Bl]
    __shared__ __align__(16) char smbuf[NSTAGE*STAGE_BYTES];
    const int t = threadIdx.x, warp = t>>5, lane = t&31;
    const int wm = (warp & 3)*32, wn = (warp >> 2)*32;
    const size_t m0 = (size_t)blockIdx.y * TM;
    const int n0 = blockIdx.x * TN;
    const int nk = K >> 4;
    uint32_t smb = smem_u32(smbuf);

    // cp.async thread assignment: 3 ops/thread
    const int rA = t>>1, hA = t&1;
    const char* gAh = (const char*)(a_hi + (m0 + rA)*(size_t)K) + hA*16;
    const char* gAl = (const char*)(a_lo + (m0 + rA)*(size_t)K) + hA*16;
    const uint32_t dA = smb + hA*2048 + rA*16;
    const int rB = (t & 127)>>1, verB = t>>7;
    const char* gB = (const char*)((verB ? w_lo : w_hi) + (size_t)(n0 + rB)*K) + hA*16;
    const uint32_t dB = smb + 8192 + verB*2048 + hA*1024 + rB*16;

    // ldmatrix lane addresses (stage 0 base)
    const uint32_t aAdr = smb + (lane>>4)*2048 + (uint32_t)(wm + (lane&15))*16;
    const uint32_t bAdr = smb + 8192 + ((lane>>3)&1)*1024
                        + (uint32_t)(wn + (lane&7) + ((lane>>4)<<3))*16;

    float acc[2][4][4];
    #pragma unroll
    for (int i=0;i<2;i++)
        #pragma unroll
        for (int j=0;j<4;j++)
            #pragma unroll
            for (int c=0;c<4;c++) acc[i][j][c] = 0.f;

    // prologue: issue stages 0,1
    #pragma unroll
    for (int s=0;s<NSTAGE-1;s++){
        uint32_t so = s*STAGE_BYTES;
        size_t ko = (size_t)s*32;
        cp_async16(dA + so,        gAh + ko);
        cp_async16(dA + so + 4096, gAl + ko);
        cp_async16(dB + so,        gB  + ko);
        CP_COMMIT();
    }

    int stg = 0;
    for (int ks = 0; ks < nk; ks++){
        CP_WAIT1();
        __syncthreads();
        uint32_t so = (uint32_t)stg*STAGE_BYTES;

        uint32_t afh[2][4], afl[2][4], bfh[4][2], bfl[4][2], tmp[4];
        #pragma unroll
        for (int mt=0; mt<2; mt++){
            LDM4(afh[mt], aAdr + so + mt*256);
            LDM4(afl[mt], aAdr + so + 4096 + mt*256);
        }
        #pragma unroll
        for (int np=0; np<2; np++){
            LDM4(tmp, bAdr + so + np*256);
            bfh[2*np][0]=tmp[0]; bfh[2*np][1]=tmp[1];
            bfh[2*np+1][0]=tmp[2]; bfh[2*np+1][1]=tmp[3];
            LDM4(tmp, bAdr + so + 2048 + np*256);
            bfl[2*np][0]=tmp[0]; bfl[2*np][1]=tmp[1];
            bfl[2*np+1][0]=tmp[2]; bfl[2*np+1][1]=tmp[3];
        }

        // issue stage ks+NSTAGE-1
        if (ks + NSTAGE - 1 < nk){
            uint32_t so2 = (uint32_t)((ks + NSTAGE - 1) % NSTAGE)*STAGE_BYTES;
            size_t ko = (size_t)(ks + NSTAGE - 1)*32;
            cp_async16(dA + so2,        gAh + ko);
            cp_async16(dA + so2 + 4096, gAl + ko);
            cp_async16(dB + so2,        gB  + ko);
        }
        CP_COMMIT();

        #pragma unroll
        for (int mt=0; mt<2; mt++)
            #pragma unroll
            for (int nt=0; nt<4; nt++){
                mma16816(acc[mt][nt], afh[mt], bfh[nt]);
                mma16816(acc[mt][nt], afl[mt], bfh[nt]);
                mma16816(acc[mt][nt], afh[mt], bfl[nt]);
            }
        stg = (stg + 1 == NSTAGE) ? 0 : stg + 1;
    }

    // ---------- epilogue ----------
    const int r0 = lane >> 2;
    const int cp2 = (lane & 3) * 2;
    #pragma unroll
    for (int mt=0; mt<2; mt++){
        #pragma unroll
        for (int nt=0; nt<4; nt++){
            int n = n0 + wn + nt*8 + cp2;
            size_t mA = m0 + wm + mt*16 + r0;
            size_t mB = mA + 8;
            float c0 = acc[mt][nt][0], c1 = acc[mt][nt][1];
            float c2 = acc[mt][nt][2], c3 = acc[mt][nt][3];
            if (EPI == 0){
                *(float2*)(outf + mA*(size_t)ldo + n) = make_float2(c0, c1);
                *(float2*)(outf + mB*(size_t)ldo + n) = make_float2(c2, c3);
            } else if (EPI == 1){
                float b0 = bias[n], b1 = bias[n+1];
                split_store(gelu_f(c0 + b0), oh, ol, mA*(size_t)ldo + n);
                split_store(gelu_f(c1 + b1), oh, ol, mA*(size_t)ldo + n + 1);
                split_store(gelu_f(c2 + b0), oh, ol, mB*(size_t)ldo + n);
                split_store(gelu_f(c3 + b1), oh, ol, mB*(size_t)ldo + n + 1);
            } else {
                float b0 = bias[n], b1 = bias[n+1];
                float g0 = gamma[n], g1 = gamma[n+1];
                float2* pA = (float2*)(resid + mA*(size_t)CC + n);
                float2* pB = (float2*)(resid + mB*(size_t)CC + n);
                float2 vA = *pA, vB = *pB;
                vA.x += g0*(c0 + b0); vA.y += g1*(c1 + b1);
                vB.x += g0*(c2 + b0); vB.y += g1*(c3 + b1);
                *pA = vA; *pB = vB;
            }
        }
    }
}

// ---------- spatial window attention (fp32 in, split bf16 out) ----------
__global__ __launch_bounds__(64) void sa_attn_kernel(const float* __restrict__ qkv,
                                                     const float* __restrict__ btab,
                                                     __nv_bfloat16* __restrict__ ohi,
                                                     __nv_bfloat16* __restrict__ olo){
    __shared__ __align__(16) float qs[LW*HD];
    __shared__ __align__(16) float ks[LW*HD];
    __shared__ __align__(16) float vs[LW*HD];
    __shared__ float bt[225];
    int win = blockIdx.x, hh = blockIdx.y;
    int l = threadIdx.x;
    int b = win >> 8;
    int wrem = win & 255;
    int wh = wrem >> 4, ww = wrem & 15;
    int i = l >> 3, j = l & 7;
    size_t n = ((size_t)(b*HH) + wh*WS + i)*WWI + ww*WS + j;

    const float4* qp = (const float4*)(qkv + n*C3 +        hh*HD);
    const float4* kp = (const float4*)(qkv + n*C3 + CC   + hh*HD);
    const float4* vp = (const float4*)(qkv + n*C3 + 2*CC + hh*HD);
    float4* qd = (float4*)&qs[l*HD];
    float4* kd = (float4*)&ks[l*HD];
    float4* vd = (float4*)&vs[l*HD];
    #pragma unroll
    for (int u=0;u<6;u++){ qd[u]=qp[u]; kd[u]=kp[u]; vd[u]=vp[u]; }
    for (int tt=l; tt<225; tt+=64) bt[tt] = btab[tt*NHEAD + hh];
    __syncthreads();

    float4 qf[6];
    #pragma unroll
    for (int u=0;u<6;u++) qf[u] = ((const float4*)&qs[l*HD])[u];

    float s[LW];
    #pragma unroll
    for (int m=0;m<LW;m++){
        const float4* kr = (const float4*)&ks[m*HD];
        float a = 0.f;
        #pragma unroll
        for (int u=0;u<6;u++){
            float4 kv = kr[u];
            a = fmaf(qf[u].x,kv.x, fmaf(qf[u].y,kv.y, fmaf(qf[u].z,kv.z, fmaf(qf[u].w,kv.w, a))));
        }
        int mi = m>>3, mj = m&7;
        s[m] = a*SCALE_ATT + bt[(i-mi+7)*15 + (j-mj+7)];
    }
    float mx = s[0];
    #pragma unroll
    for (int m=1;m<LW;m++) mx = fmaxf(mx, s[m]);
    float sum = 0.f;
    #pragma unroll
    for (int m=0;m<LW;m++){ s[m] = __expf(s[m]-mx); sum += s[m]; }
    float inv = 1.f/sum;

    float o[HD];
    #pragma unroll
    for (int u=0;u<HD;u++) o[u] = 0.f;
    #pragma unroll
    for (int m=0;m<LW;m++){
        float p = s[m];
        const float* vr = &vs[m*HD];
        #pragma unroll
        for (int u=0;u<HD;u++) o[u] = fmaf(p, vr[u], o[u]);
    }
    size_t ob = n*CC + hh*HD;
    #pragma unroll
    for (int u=0;u<HD;u++) split_store(o[u]*inv, ohi, olo, ob + u);
}

// ---------- channel attention ----------
__global__ void zero_kernel(float* p, int n){
    int idx = blockIdx.x*blockDim.x + threadIdx.x;
    if (idx < n) p[idx] = 0.f;
}
__global__ __launch_bounds__(256) void ca_gram_kernel(const float* __restrict__ qkv,
                                                      float* __restrict__ gram){
    __shared__ __align__(16) float qs[256*HD];
    __shared__ __align__(16) float ks[256*HD];
    int bh = blockIdx.y; int b = bh >> 3; int hh = bh & 7;
    int chunk = blockIdx.x;
    int t = threadIdx.x;
    size_t n = (size_t)b*(HH*WWI) + (size_t)chunk*256 + t;
    const float4* qp = (const float4*)(qkv + n*C3 +      hh*HD);
    const float4* kp = (const float4*)(qkv + n*C3 + CC + hh*HD);
    float4* qd = (float4*)&qs[t*HD];
    float4* kd = (float4*)&ks[t*HD];
    #pragma unroll
    for (int u=0;u<6;u++){ qd[u]=qp[u]; kd[u]=kp[u]; }
    __syncthreads();

    int p0 = t, p1 = t + 256, p2 = t + 512;
    int d0 = p0/HD, e0 = p0 - d0*HD;
    int d1 = p1/HD, e1 = p1 - d1*HD;
    int d2 = p2/HD, e2 = p2 - d2*HD;
    bool has2 = (p2 < 576);
    float a0=0.f, a1=0.f, a2=0.f;
    for (int l=0;l<256;l++){
        const float* qrow = &qs[l*HD];
        const float* krow = &ks[l*HD];
        a0 = fmaf(qrow[d0], krow[e0], a0);
        a1 = fmaf(qrow[d1], krow[e1], a1);
        if (has2) a2 = fmaf(qrow[d2], krow[e2], a2);
    }
    atomicAdd(&gram[bh*576 + p0], a0);
    atomicAdd(&gram[bh*576 + p1], a1);
    if (has2) atomicAdd(&gram[bh*576 + p2], a2);
}
__global__ void ca_softmax_kernel(const float* __restrict__ gram, float* __restrict__ attn){
    int bh = blockIdx.x; int d = threadIdx.x;
    if (d >= HD) return;
    const float* r = gram + bh*576 + d*HD;
    float v[HD];
    float mx = -1e30f;
    #pragma unroll
    for (int e=0;e<HD;e++){ v[e] = r[e]*SCALE_ATT; mx = fmaxf(mx, v[e]); }
    float sum = 0.f;
    #pragma unroll
    for (int e=0;e<HD;e++){ v[e] = __expf(v[e]-mx); sum += v[e]; }
    float inv = 1.f/sum;
    #pragma unroll
    for (int e=0;e<HD;e++) attn[bh*576 + d*HD + e] = v[e]*inv;
}
__global__ __launch_bounds__(192) void ca_apply_kernel(const float* __restrict__ qkv,
                                                       const float* __restrict__ attn,
                                                       __nv_bfloat16* __restrict__ ohi,
                                                       __nv_bfloat16* __restrict__ olo){
    __shared__ float at[NHEAD*HD*HD];
    __shared__ float vsm[CC];
    int t = threadIdx.x;
    size_t n0 = (size_t)blockIdx.x * 32;
    int b = (int)(n0 >> 14);
    for (int idx=t; idx<NHEAD*HD*HD; idx+=192) at[idx] = attn[(size_t)b*NHEAD*HD*HD + idx];
    __syncthreads();
    int hh = t / HD, d = t - hh*HD;
    float ar[HD];
    #pragma unroll
    for (int e=0;e<HD;e++) ar[e] = at[hh*576 + d*HD + e];
    for (int tok=0; tok<32; tok++){
        size_t n = n0 + tok;
        __syncthreads();
        vsm[t] = qkv[n*C3 + 2*CC + t];
        __syncthreads();
        float o = 0.f;
        #pragma unroll
        for (int e=0;e<HD;e++) o = fmaf(ar[e], vsm[hh*HD + e], o);
        split_store(o, ohi, olo, n*CC + t);
    }
}

// ---------- launch ----------
extern "C" void kernel_launch(void* const* d_in, const int* in_sizes, int n_in,
                              void* d_out, int out_size)
{
    const float* x           = (const float*)d_in[0];
    const float* sa_norm_w   = (const float*)d_in[1];
    const float* sa_norm_b   = (const float*)d_in[2];
    const float* sa_qkv_w    = (const float*)d_in[3];
    const float* sa_proj_w   = (const float*)d_in[4];
    const float* sa_proj_b   = (const float*)d_in[5];
    const float* sa_bias_tab = (const float*)d_in[6];
    const float* ca_norm_w   = (const float*)d_in[7];
    const float* ca_norm_b   = (const float*)d_in[8];
    const float* ca_qkv_w    = (const float*)d_in[9];
    const float* ca_proj_w   = (const float*)d_in[10];
    const float* ca_proj_b   = (const float*)d_in[11];
    const float* ffn_norm_w  = (const float*)d_in[12];
    const float* ffn_norm_b  = (const float*)d_in[13];
    const float* ffn_w1      = (const float*)d_in[14];
    const float* ffn_b1      = (const float*)d_in[15];
    const float* ffn_w2      = (const float*)d_in[16];
    const float* ffn_b2      = (const float*)d_in[17];
    const float* gamma1      = (const float*)d_in[18];
    const float* gamma2      = (const float*)d_in[19];
    const float* gamma3      = (const float*)d_in[20];
    float* y = (float*)d_out;

    float *xt, *qkv, *gram, *attn;
    __nv_bfloat16 *ah, *al, *fh, *fl, *wh, *wl;
    cudaGetSymbolAddress((void**)&xt,   g_xt);
    cudaGetSymbolAddress((void**)&qkv,  g_qkv);
    cudaGetSymbolAddress((void**)&gram, g_gram);
    cudaGetSymbolAddress((void**)&attn, g_attn);
    cudaGetSymbolAddress((void**)&ah,   g_ah);
    cudaGetSymbolAddress((void**)&al,   g_al);
    cudaGetSymbolAddress((void**)&fh,   g_hh);
    cudaGetSymbolAddress((void**)&fl,   g_hl);
    cudaGetSymbolAddress((void**)&wh,   g_wh);
    cudaGetSymbolAddress((void**)&wl,   g_wl);

    WSrc ws;
    ws.p[0] = sa_qkv_w; ws.p[1] = sa_proj_w; ws.p[2] = ca_qkv_w;
    ws.p[3] = ca_proj_w; ws.p[4] = ffn_w1; ws.p[5] = ffn_w2;
    wconv_all<<<(W_TOT+255)/256, 256>>>(ws, wh, wl);

    dim3 tb(32,8);
    dim3 tg(WWI/32, CC/32, BB*HH);
    nchw_to_nhwc<<<tg, tb>>>(x, xt);

    const int MT = NTOK/TM;   // 1024

    // ---- spatial window attention ----
    ln_kernel<<<NTOK/4, 128>>>(xt, sa_norm_w, sa_norm_b, ah, al);
    gemm_mma<0><<<dim3(C3/TN, MT), 256>>>(ah, al, wh+W_SAQKV, wl+W_SAQKV,
        nullptr, qkv, nullptr, nullptr, nullptr, nullptr, CC, C3);
    sa_attn_kernel<<<dim3(NWIN, NHEAD), 64>>>(qkv, sa_bias_tab, ah, al);
    gemm_mma<2><<<dim3(CC/TN, MT), 256>>>(ah, al, wh+W_SAPRJ, wl+W_SAPRJ,
        sa_proj_b, nullptr, nullptr, nullptr, gamma1, xt, CC, CC);

    // ---- channel attention ----
    ln_kernel<<<NTOK/4, 128>>>(xt, ca_norm_w, ca_norm_b, ah, al);
    gemm_mma<0><<<dim3(C3/TN, MT), 256>>>(ah, al, wh+W_CAQKV, wl+W_CAQKV,
        nullptr, qkv, nullptr, nullptr, nullptr, nullptr, CC, C3);
    zero_kernel<<<(BB*NHEAD*HD*HD + 255)/256, 256>>>(gram, BB*NHEAD*HD*HD);
    ca_gram_kernel<<<dim3(64, BB*NHEAD), 256>>>(qkv, gram);
    ca_softmax_kernel<<<BB*NHEAD, 32>>>(gram, attn);
    ca_apply_kernel<<<NTOK/32, 192>>>(qkv, attn, ah, al);
    gemm_mma<2><<<dim3(CC/TN, MT), 256>>>(ah, al, wh+W_CAPRJ, wl+W_CAPRJ,
        ca_proj_b, nullptr, nullptr, nullptr, gamma2, xt, CC, CC);

    // ---- gated FFN ----
    ln_kernel<<<NTOK/4, 128>>>(xt, ffn_norm_w, ffn_norm_b, ah, al);
    gemm_mma<1><<<dim3(FFND/TN, MT), 256>>>(ah, al, wh+W_FFN1, wl+W_FFN1,
        ffn_b1, nullptr, fh, fl, nullptr, nullptr, CC, FFND);
    gemm_mma<2><<<dim3(CC/TN, MT), 256>>>(fh, fl, wh+W_FFN2, wl+W_FFN2,
        ffn_b2, nullptr, nullptr, nullptr, gamma3, xt, FFND, CC);

    nhwc_to_nchw<<<tg, tb>>>(xt, y);
}